// round 6
// baseline (speedup 1.0000x reference)
#include <cuda_runtime.h>
#include <cuda_fp16.h>
#include <math.h>

#define EPS 1e-8f
#define NB 64
#define NO 64
#define NI 1152
#define ND 16
#define INVT1 5.0e-4f            /* 0.01*(1-0.95)   */
#define INVT2 9.75e-4f           /* 0.01*(1-0.9025) */

typedef unsigned long long ull;

/* packed f32x2 helpers */
#define PACK2(dst, lo, hi) \
    asm("mov.b64 %0, {%1, %2};" : "=l"(dst) : "r"(__float_as_uint(lo)), "r"(__float_as_uint(hi)))
#define FMA2(acc, a, b) \
    asm("fma.rn.f32x2 %0, %1, %2, %0;" : "+l"(acc) : "l"(a), "l"(b))
#define ADD2(d, a, b) \
    asm("add.rn.f32x2 %0, %1, %2;" : "=l"(d) : "l"(a), "l"(b))
#define UNPK2(lo, hi, v) do { unsigned _ul, _uh; \
    asm("mov.b64 {%0, %1}, %2;" : "=r"(_ul), "=r"(_uh) : "l"(v)); \
    lo = __uint_as_float(_ul); hi = __uint_as_float(_uh); } while (0)
#define STEP(acc, av, wd) do { ull _t; \
    asm("mov.b64 %0, {%1, %1};" : "=l"(_t) : "r"(__float_as_uint(av))); \
    FMA2(acc, _t, wd); } while (0)

/* unpack 2 x uint4 (16 halves) -> 16 floats */
#define UNPACK16(v, x0, x1) do { float2 _f; \
    _f = __half22float2(*(const __half2*)&(x0).x); (v)[0]=_f.x; (v)[1]=_f.y; \
    _f = __half22float2(*(const __half2*)&(x0).y); (v)[2]=_f.x; (v)[3]=_f.y; \
    _f = __half22float2(*(const __half2*)&(x0).z); (v)[4]=_f.x; (v)[5]=_f.y; \
    _f = __half22float2(*(const __half2*)&(x0).w); (v)[6]=_f.x; (v)[7]=_f.y; \
    _f = __half22float2(*(const __half2*)&(x1).x); (v)[8]=_f.x; (v)[9]=_f.y; \
    _f = __half22float2(*(const __half2*)&(x1).y); (v)[10]=_f.x; (v)[11]=_f.y; \
    _f = __half22float2(*(const __half2*)&(x1).z); (v)[12]=_f.x; (v)[13]=_f.y; \
    _f = __half22float2(*(const __half2*)&(x1).w); (v)[14]=_f.x; (v)[15]=_f.y; \
} while (0)

/* ---------------- scratch (device globals: allocation-free) ---------------- */
__device__ __half g_Vh[(size_t)NB * NI * NO * ND];  /* [b][i][o][e] fp16, 151 MB */
__device__ float g_ai[NB * NI];
__device__ float g_asum[NB];
__device__ float g_S1S[NB * NO * ND];
__device__ float g_S1Q[NB * NO * ND];
__device__ float g_mean0[NB * NO * ND];
__device__ float g_inv2[NB * NO * ND];
__device__ float g_c[NB * NO];
__device__ float g_S[NB * NO * 33];

/* ---------------- K0 ---------------- */
__global__ void k0_ai(const float* __restrict__ u) {
    int b = blockIdx.x, tid = threadIdx.x;
    for (int k = tid; k < 1024; k += 256) {
        g_S1S[b * 1024 + k] = 0.f;
        g_S1Q[b * 1024 + k] = 0.f;
    }
    float part = 0.f;
    for (int i = tid; i < NI; i += 256) {
        const float* ur = u + (b * NI + i) * ND;
        float s = 0.f;
#pragma unroll
        for (int d = 0; d < ND; d++) { float x = ur[d] + EPS; s += x * x; }
        float a = sqrtf(s);
        g_ai[b * NI + i] = a;
        part += a;
    }
    __shared__ float sm[256];
    sm[tid] = part; __syncthreads();
    for (int s = 128; s > 0; s >>= 1) { if (tid < s) sm[tid] += sm[tid + s]; __syncthreads(); }
    if (tid == 0) g_asum[b] = sm[0];
}

/* ---------------- K1: votes GEMM, packed f32x2, fp16 stores ---------------- */
__global__ __launch_bounds__(256) void k1_votes(
    const float4* __restrict__ u4, const float4* __restrict__ W4,
    const float* __restrict__ bias)
{
    int o = blockIdx.x, i0 = blockIdx.y * 32;
    int tid = threadIdx.x, p = tid & 7, i_idx = tid >> 3;

    __shared__ float4 us[8][32][4];

    ull w2[16];
    {
        size_t base = ((size_t)o * NI + i0 + i_idx) * ND;
        const float4* r0 = W4 + (base + 2 * p) * 4;
        const float4* r1 = W4 + (base + 2 * p + 1) * 4;
        float4 e0[4], e1[4];
#pragma unroll
        for (int k = 0; k < 4; k++) { e0[k] = r0[k]; e1[k] = r1[k]; }
#pragma unroll
        for (int k = 0; k < 4; k++) {
            PACK2(w2[4 * k + 0], e0[k].x, e1[k].x);
            PACK2(w2[4 * k + 1], e0[k].y, e1[k].y);
            PACK2(w2[4 * k + 2], e0[k].z, e1[k].z);
            PACK2(w2[4 * k + 3], e0[k].w, e1[k].w);
        }
    }
    ull bias2;
    PACK2(bias2, bias[o * ND + 2 * p] + EPS, bias[o * ND + 2 * p + 1] + EPS);

    __half2* Vh2 = (__half2*)g_Vh;

    for (int g = 0; g < 8; g++) {
        __syncthreads();
        for (int n = tid; n < 1024; n += 256) {
            int bs = n >> 7, rem = n & 127, ii = rem >> 2, d4 = rem & 3;
            us[bs][ii][d4] = u4[((size_t)(g * 8 + bs) * NI + i0 + ii) * 4 + d4];
        }
        __syncthreads();

#pragma unroll
        for (int bs = 0; bs < 8; bs++) {
            float4 a0 = us[bs][i_idx][0], a1 = us[bs][i_idx][1];
            float4 a2 = us[bs][i_idx][2], a3 = us[bs][i_idx][3];
            ull va = bias2, vb = 0ull;
            STEP(va, a0.x, w2[0]);  STEP(vb, a0.y, w2[1]);
            STEP(va, a0.z, w2[2]);  STEP(vb, a0.w, w2[3]);
            STEP(va, a1.x, w2[4]);  STEP(vb, a1.y, w2[5]);
            STEP(va, a1.z, w2[6]);  STEP(vb, a1.w, w2[7]);
            STEP(va, a2.x, w2[8]);  STEP(vb, a2.y, w2[9]);
            STEP(va, a2.z, w2[10]); STEP(vb, a2.w, w2[11]);
            STEP(va, a3.x, w2[12]); STEP(vb, a3.y, w2[13]);
            STEP(va, a3.z, w2[14]); STEP(vb, a3.w, w2[15]);
            ull v2; ADD2(v2, va, vb);
            float lo, hi; UNPK2(lo, hi, v2);
            size_t idx = (((size_t)(g * 8 + bs) * NI + i0 + i_idx) * NO + o) * 8 + p;
            Vh2[idx] = __floats2half2_rn(lo, hi);
        }
    }
}

/* ---------------- K1s: stage-1 sums, uint4 loads, unroll 4 ----------------
 * grid (b=64, 18 chunks of 64 i); thread = (o, i-parity, e-half).
 */
__global__ __launch_bounds__(256) void k1s_sums(void)
{
    int b = blockIdx.x, i0 = blockIdx.y * 64;
    int tid = threadIdx.x;
    int o = tid >> 2, sub = tid & 3, ipar = sub >> 1, h = sub & 1;

    float S[8], Q[8];
#pragma unroll
    for (int k = 0; k < 8; k++) { S[k] = 0.f; Q[k] = 0.f; }

    const uint4* base = (const uint4*)(g_Vh +
        (((size_t)b * NI + i0 + ipar) * NO + o) * ND + h * 8);
    const float* aip = g_ai + b * NI + i0 + ipar;

#pragma unroll 4
    for (int ii = 0; ii < 32; ii++) {
        float ai = __ldg(aip + 2 * ii);
        uint4 raw = base[ii * 256];      /* step 2 i's = 4096 B = 256 uint4 */
        float v[8];
        float2 f;
        f = __half22float2(*(const __half2*)&raw.x); v[0]=f.x; v[1]=f.y;
        f = __half22float2(*(const __half2*)&raw.y); v[2]=f.x; v[3]=f.y;
        f = __half22float2(*(const __half2*)&raw.z); v[4]=f.x; v[5]=f.y;
        f = __half22float2(*(const __half2*)&raw.w); v[6]=f.x; v[7]=f.y;
#pragma unroll
        for (int k = 0; k < 8; k++) {
            float t = ai * v[k];
            S[k] += t;
            Q[k] = fmaf(t, v[k], Q[k]);
        }
    }
    int idx = (b * NO + o) * ND + h * 8;
#pragma unroll
    for (int k = 0; k < 8; k++) {
        atomicAdd(&g_S1S[idx + k], S[k]);
        atomicAdd(&g_S1Q[idx + k], Q[k]);
    }
}

/* ---------------- K1b: per-(b,o) stats ---------------- */
__global__ void k1b_stats(const float* __restrict__ beta_a,
                          const float* __restrict__ beta_u)
{
    int idx = blockIdx.x * 256 + threadIdx.x;
    int bo = idx >> 4, e = idx & 15;
    int o = bo & 63, b = bo >> 6;
    float S = g_S1S[idx] * (1.0f / NO);
    float Q = g_S1Q[idx] * (1.0f / NO);
    float rs  = g_asum[b] * (1.0f / NO);
    float inv = 1.0f / (rs + EPS);
    float m   = S * inv;
    float var = (Q - 2.0f * m * S + m * m * rs) * inv + 1e-4f;
    float lv  = __logf(var);
    float lsum = lv;
#pragma unroll
    for (int off = 8; off; off >>= 1) lsum += __shfl_xor_sync(0xffffffffu, lsum, off);
    float cost = rs * (16.0f * beta_u[o] + lsum);
    float aj   = 1.0f / (1.0f + __expf(-INVT1 * (beta_a[o] - cost)));
    float p1   = sqrtf(2.0f * 3.14159265358979323846f * __expf(lsum) + EPS);
    g_mean0[idx] = m;
    g_inv2[idx]  = 1.0f / (2.0f * var + EPS);
    if (e == 0) g_c[bo] = aj / (p1 + EPS);
    g_S[bo * 33 + e] = 0.f;
    g_S[bo * 33 + 16 + e] = 0.f;
    if (e == 0) g_S[bo * 33 + 32] = 0.f;
}

/* ---------------- K2: fused e-step + m-step-2, V held in registers --------
 * grid (b=64, 9 regions of 128 i); threads 256 = (isub=4) x (o=64).
 * Per region: 8 subtiles of 16 i. Each thread keeps its 4 i-rows of V in
 * 8 uint4 regs across the ap->denom->accumulate phases (V read ONCE).
 * Final flush: smem pre-reduce + atomics, once per block.
 */
__global__ __launch_bounds__(256, 2) void k2_route(void)
{
    __shared__ float sbuf[8448];      /* aps[16*64] + sden[16]; overlay accsm */
    float* aps  = sbuf;
    float* sden = sbuf + 1024;

    int b = blockIdx.x, ibase = blockIdx.y * 128;
    int tid = threadIdx.x, o = tid & 63, isub = tid >> 6;
    int bo = b * NO + o;

    float m[16], iv[16];
    {
        const float4* pm = (const float4*)(g_mean0 + bo * ND);
        const float4* pi = (const float4*)(g_inv2  + bo * ND);
#pragma unroll
        for (int k = 0; k < 4; k++) {
            float4 a = pm[k], c = pi[k];
            m[4*k]=a.x; m[4*k+1]=a.y; m[4*k+2]=a.z; m[4*k+3]=a.w;
            iv[4*k]=c.x; iv[4*k+1]=c.y; iv[4*k+2]=c.z; iv[4*k+3]=c.w;
        }
    }
    float cc = g_c[bo];
    const uint4* V4 = (const uint4*)g_Vh;

    float accw = 0.f, accv[16], accq[16];
#pragma unroll
    for (int e = 0; e < 16; e++) { accv[e] = 0.f; accq[e] = 0.f; }

    for (int t = 0; t < 8; t++) {
        int i0 = ibase + t * 16;
        uint4 vr[8];
        float ap_r[4];

#pragma unroll
        for (int j = 0; j < 4; j++) {
            int il = j * 4 + isub;
            size_t adr = (((size_t)b * NI + i0 + il) * NO + o) * 2;
            vr[2*j]   = V4[adr];
            vr[2*j+1] = V4[adr + 1];
            float v[16];
            UNPACK16(v, vr[2*j], vr[2*j+1]);
            float la = 0.f;
#pragma unroll
            for (int e = 0; e < 16; e++) { float d = v[e] - m[e]; la = fmaf(d * d, iv[e], la); }
            float ap = cc * __expf(-la);
            ap_r[j] = ap;
            aps[il * 64 + o] = ap;
        }
        __syncthreads();

        if (tid < 128) {
            int il = tid >> 3, seg = tid & 7;
            const float* row = aps + il * 64 + seg * 8;
            float s = row[0] + row[1] + row[2] + row[3]
                    + row[4] + row[5] + row[6] + row[7];
            s += __shfl_xor_sync(0xffffffffu, s, 1);
            s += __shfl_xor_sync(0xffffffffu, s, 2);
            s += __shfl_xor_sync(0xffffffffu, s, 4);
            if (seg == 0)
                sden[il] = __ldg(&g_ai[b * NI + i0 + il]) / (s + EPS);
        }
        __syncthreads();

#pragma unroll
        for (int j = 0; j < 4; j++) {
            int il = j * 4 + isub;
            float wt = ap_r[j] * sden[il];
            float v[16];
            UNPACK16(v, vr[2*j], vr[2*j+1]);
            accw += wt;
#pragma unroll
            for (int e = 0; e < 16; e++) {
                accv[e] = fmaf(wt, v[e], accv[e]);
                accq[e] = fmaf(wt * v[e], v[e], accq[e]);
            }
        }
        __syncthreads();   /* protect sden/aps before next subtile */
    }

    /* flush: smem pre-reduce over isub, then atomics */
    float* accsm = sbuf;
#pragma unroll
    for (int e = 0; e < 16; e++) {
        accsm[e * 256 + isub * 64 + o]        = accv[e];
        accsm[(16 + e) * 256 + isub * 64 + o] = accq[e];
    }
    accsm[32 * 256 + isub * 64 + o] = accw;
    __syncthreads();
    {
        int o2 = tid & 63, ks = tid >> 6;
        for (int k = ks; k < 33; k += 4) {
            const float* r = accsm + k * 256 + o2;
            float s = r[0] + r[64] + r[128] + r[192];
            atomicAdd(&g_S[(b * NO + o2) * 33 + k], s);
        }
    }
}

/* ---------------- K3: finalize + output ---------------- */
__global__ void k3_final(const float* __restrict__ beta_a,
                         const float* __restrict__ beta_u,
                         float* __restrict__ out)
{
    int bo = blockIdx.x * 256 + threadIdx.x;
    if (bo >= NB * NO) return;
    int o = bo & 63;
    const float* s = g_S + bo * 33;
    float rs  = s[32];
    float inv = 1.0f / (rs + EPS);
    float bu  = beta_u[o];
    float mm[16];
    float cost = 0.f, norm2 = 0.f;
#pragma unroll
    for (int e = 0; e < 16; e++) {
        float sv = s[e], sq = s[16 + e];
        float me = sv * inv;
        float var = (sq - 2.0f * me * sv + me * me * rs) * inv + 1e-4f;
        cost += bu + __logf(var);
        mm[e] = me;
        float t = me + EPS;
        norm2 = fmaf(t, t, norm2);
    }
    cost *= rs;
    float aj = 1.0f / (1.0f + __expf(-INVT2 * (beta_a[o] - cost)));
    float scale = aj / (sqrtf(norm2) + EPS);
#pragma unroll
    for (int e = 0; e < 16; e++) out[bo * ND + e] = mm[e] * scale;
}

/* ---------------- launch ---------------- */
extern "C" void kernel_launch(void* const* d_in, const int* in_sizes, int n_in,
                              void* d_out, int out_size)
{
    const float* u      = (const float*)d_in[0];
    const float* W      = (const float*)d_in[1];
    const float* beta_a = (const float*)d_in[2];
    const float* beta_u = (const float*)d_in[3];
    const float* bias   = (const float*)d_in[4];
    float* out = (float*)d_out;

    k0_ai<<<NB, 256>>>(u);
    k1_votes<<<dim3(NO, 36), 256>>>((const float4*)u, (const float4*)W, bias);
    k1s_sums<<<dim3(NB, 18), 256>>>();
    k1b_stats<<<256, 256>>>(beta_a, beta_u);
    k2_route<<<dim3(NB, 9), 256>>>();
    k3_final<<<16, 256>>>(beta_a, beta_u, out);
}